// round 2
// baseline (speedup 1.0000x reference)
#include <cuda_runtime.h>
#include <cuda_bf16.h>

// ---------------- problem constants ----------------
#define BATCH 4
#define SEQ 4096
#define DMODEL 1024
#define WIN 256
#define NWIN 31              // window starts 0,128,...,3840
#define NBW (BATCH * NWIN)   // 124
#define MTOK (BATCH * SEQ)   // 16384

// ---------------- scratch (static device, no allocs) ----------------
__device__ float g_q[(size_t)BATCH * SEQ * DMODEL];
__device__ float g_k[(size_t)BATCH * SEQ * DMODEL];
__device__ float g_v[(size_t)BATCH * SEQ * DMODEL];
__device__ float g_s[(size_t)NBW * WIN * WIN];          // scores/probs
__device__ float g_ow[(size_t)NBW * WIN * DMODEL];      // per-window outputs
__device__ float g_y[(size_t)BATCH * SEQ * DMODEL];

// ---------------- SGEMM: C[M,N] = A[M,K] @ B[K,N] + bias[N] ----------------
#define GBM 128
#define GBN 128
#define GBK 8

__global__ __launch_bounds__(256) void sgemm_bias(
    const float* __restrict__ A, const float* __restrict__ B,
    const float* __restrict__ bias, float* __restrict__ C,
    int M, int N, int K)
{
    __shared__ float As[GBK][GBM];
    __shared__ float Bs[GBK][GBN];

    const int tid = threadIdx.x;
    const int bx = blockIdx.x * GBN;
    const int by = blockIdx.y * GBM;

    const int tc = tid & 15;
    const int tr = tid >> 4;

    const int arow = tid >> 1;
    const int acol = (tid & 1) * 4;
    const int brow = tid >> 5;
    const int bcol = (tid & 31) * 4;

    const float* Aptr = A + (size_t)(by + arow) * K + acol;
    const float* Bptr = B + (size_t)brow * N + bx + bcol;

    float acc[8][8];
#pragma unroll
    for (int i = 0; i < 8; i++)
#pragma unroll
        for (int j = 0; j < 8; j++) acc[i][j] = 0.f;

    for (int k0 = 0; k0 < K; k0 += GBK) {
        float4 av = *(const float4*)(Aptr + k0);
        float4 bv = *(const float4*)(Bptr + (size_t)k0 * N);

        As[acol + 0][arow] = av.x;
        As[acol + 1][arow] = av.y;
        As[acol + 2][arow] = av.z;
        As[acol + 3][arow] = av.w;
        *(float4*)&Bs[brow][bcol] = bv;
        __syncthreads();

#pragma unroll
        for (int kk = 0; kk < GBK; kk++) {
            float a[8], b[8];
            *(float4*)&a[0] = *(const float4*)&As[kk][tr * 8];
            *(float4*)&a[4] = *(const float4*)&As[kk][tr * 8 + 4];
            *(float4*)&b[0] = *(const float4*)&Bs[kk][tc * 8];
            *(float4*)&b[4] = *(const float4*)&Bs[kk][tc * 8 + 4];
#pragma unroll
            for (int i = 0; i < 8; i++)
#pragma unroll
                for (int j = 0; j < 8; j++)
                    acc[i][j] += a[i] * b[j];
        }
        __syncthreads();
    }

#pragma unroll
    for (int i = 0; i < 8; i++) {
        const int r = by + tr * 8 + i;
#pragma unroll
        for (int j = 0; j < 8; j += 4) {
            const int c = bx + tc * 8 + j;
            float4 o;
            o.x = acc[i][j + 0] + bias[c + 0];
            o.y = acc[i][j + 1] + bias[c + 1];
            o.z = acc[i][j + 2] + bias[c + 2];
            o.w = acc[i][j + 3] + bias[c + 3];
            *(float4*)&C[(size_t)r * N + c] = o;
        }
    }
}

// ---------------- scores: S = scale * Qw @ Kw^T (per window) ----------------
// 64x64 tile, K-tile 16, 256 threads, 4x4 microtile. Full-D contraction (1024).
#define ST 64
#define SKT 16

__global__ __launch_bounds__(256) void win_scores(
    const float* __restrict__ q, const float* __restrict__ k,
    float* __restrict__ s)
{
    const int bw = blockIdx.z;
    const int b = bw / NWIN;
    const int w = bw - b * NWIN;
    const int g0 = 128 * w;

    const float* Q = q + ((size_t)b * SEQ + g0) * DMODEL;
    const float* K = k + ((size_t)b * SEQ + g0) * DMODEL;
    float* S = s + (size_t)bw * WIN * WIN;

    __shared__ float Qs[SKT][ST];
    __shared__ float Ks[SKT][ST];

    const int tid = threadIdx.x;
    const int by = blockIdx.y * ST;   // query-row tile
    const int bx = blockIdx.x * ST;   // key-row tile

    const int lr = tid >> 2;          // 0..63
    const int lc = (tid & 3) * 4;     // 0,4,8,12
    const int tr = tid >> 4;          // 0..15
    const int tc = tid & 15;          // 0..15

    float acc[4][4];
#pragma unroll
    for (int i = 0; i < 4; i++)
#pragma unroll
        for (int j = 0; j < 4; j++) acc[i][j] = 0.f;

    for (int k0 = 0; k0 < DMODEL; k0 += SKT) {
        float4 qa = *(const float4*)&Q[(size_t)(by + lr) * DMODEL + k0 + lc];
        float4 ka = *(const float4*)&K[(size_t)(bx + lr) * DMODEL + k0 + lc];
        Qs[lc + 0][lr] = qa.x; Qs[lc + 1][lr] = qa.y;
        Qs[lc + 2][lr] = qa.z; Qs[lc + 3][lr] = qa.w;
        Ks[lc + 0][lr] = ka.x; Ks[lc + 1][lr] = ka.y;
        Ks[lc + 2][lr] = ka.z; Ks[lc + 3][lr] = ka.w;
        __syncthreads();

#pragma unroll
        for (int kk = 0; kk < SKT; kk++) {
            float a[4], bb[4];
            *(float4*)&a[0]  = *(const float4*)&Qs[kk][tr * 4];
            *(float4*)&bb[0] = *(const float4*)&Ks[kk][tc * 4];
#pragma unroll
            for (int i = 0; i < 4; i++)
#pragma unroll
                for (int j = 0; j < 4; j++)
                    acc[i][j] += a[i] * bb[j];
        }
        __syncthreads();
    }

    const float scale = 0.125f;
#pragma unroll
    for (int i = 0; i < 4; i++) {
        const int r = by + tr * 4 + i;
        float4 o;
        o.x = acc[i][0] * scale; o.y = acc[i][1] * scale;
        o.z = acc[i][2] * scale; o.w = acc[i][3] * scale;
        *(float4*)&S[(size_t)r * WIN + bx + tc * 4] = o;
    }
}

// ---------------- softmax over 256-wide rows (warp per row) ----------------
__global__ __launch_bounds__(256) void win_softmax(float* __restrict__ s)
{
    const int row = blockIdx.x * 8 + (threadIdx.x >> 5);
    const int lane = threadIdx.x & 31;
    float* r = s + (size_t)row * WIN;

    float v[8];
    float m = -1e30f;
#pragma unroll
    for (int j = 0; j < 8; j++) {
        v[j] = r[lane + 32 * j];
        m = fmaxf(m, v[j]);
    }
#pragma unroll
    for (int o = 16; o > 0; o >>= 1)
        m = fmaxf(m, __shfl_xor_sync(0xffffffffu, m, o));

    float sum = 0.f;
#pragma unroll
    for (int j = 0; j < 8; j++) { v[j] = expf(v[j] - m); sum += v[j]; }
#pragma unroll
    for (int o = 16; o > 0; o >>= 1)
        sum += __shfl_xor_sync(0xffffffffu, sum, o);
    const float inv = 1.f / sum;

#pragma unroll
    for (int j = 0; j < 8; j++)
        r[lane + 32 * j] = v[j] * inv;
}

// ---------------- PV: O[256,1024] = P[256,256] @ Vw[256,1024] ----------------
// Same 128x128x8 structure as sgemm_bias, batched over windows, no bias.
__global__ __launch_bounds__(256) void win_pv(
    const float* __restrict__ p, const float* __restrict__ v,
    float* __restrict__ ow)
{
    const int bw = blockIdx.z;
    const int b = bw / NWIN;
    const int w = bw - b * NWIN;
    const int g0 = 128 * w;

    const float* A = p + (size_t)bw * WIN * WIN;                 // [256,256]
    const float* B = v + ((size_t)b * SEQ + g0) * DMODEL;        // [256,1024]
    float* C = ow + (size_t)bw * WIN * DMODEL;

    __shared__ float As[GBK][GBM];
    __shared__ float Bs[GBK][GBN];

    const int tid = threadIdx.x;
    const int bx = blockIdx.x * GBN;
    const int by = blockIdx.y * GBM;

    const int tc = tid & 15;
    const int tr = tid >> 4;
    const int arow = tid >> 1;
    const int acol = (tid & 1) * 4;
    const int brow = tid >> 5;
    const int bcol = (tid & 31) * 4;

    float acc[8][8];
#pragma unroll
    for (int i = 0; i < 8; i++)
#pragma unroll
        for (int j = 0; j < 8; j++) acc[i][j] = 0.f;

    for (int k0 = 0; k0 < WIN; k0 += GBK) {
        float4 av = *(const float4*)&A[(size_t)(by + arow) * WIN + acol + k0];
        float4 bv = *(const float4*)&B[(size_t)(k0 + brow) * DMODEL + bx + bcol];

        As[acol + 0][arow] = av.x;
        As[acol + 1][arow] = av.y;
        As[acol + 2][arow] = av.z;
        As[acol + 3][arow] = av.w;
        *(float4*)&Bs[brow][bcol] = bv;
        __syncthreads();

#pragma unroll
        for (int kk = 0; kk < GBK; kk++) {
            float a[8], bb[8];
            *(float4*)&a[0] = *(const float4*)&As[kk][tr * 8];
            *(float4*)&a[4] = *(const float4*)&As[kk][tr * 8 + 4];
            *(float4*)&bb[0] = *(const float4*)&Bs[kk][tc * 8];
            *(float4*)&bb[4] = *(const float4*)&Bs[kk][tc * 8 + 4];
#pragma unroll
            for (int i = 0; i < 8; i++)
#pragma unroll
                for (int j = 0; j < 8; j++)
                    acc[i][j] += a[i] * bb[j];
        }
        __syncthreads();
    }

#pragma unroll
    for (int i = 0; i < 8; i++) {
        const int r = by + tr * 8 + i;
#pragma unroll
        for (int j = 0; j < 8; j += 4)
            *(float4*)&C[(size_t)r * DMODEL + bx + tc * 8 + j] =
                *(float4*)&acc[i][j];
    }
}

// ---------------- combine: gather overlapping windows, normalize ----------------
__global__ __launch_bounds__(256) void combine_windows(
    const float* __restrict__ ow, float* __restrict__ y)
{
    const int idx = blockIdx.x * 256 + threadIdx.x;
    const int c = idx & (DMODEL - 1);
    const int bt = idx >> 10;
    const int t = bt & (SEQ - 1);
    const int b = bt >> 12;

    const int w1 = t >> 7;
    float val = 0.f, cnt = 0.f;
#pragma unroll
    for (int dw = -1; dw <= 0; dw++) {
        const int w = w1 + dw;
        if (w < 0 || w >= NWIN) continue;
        const int pos = t - 128 * w;
        if (pos < 0 || pos >= WIN) continue;
        val += ow[(((size_t)(b * NWIN + w)) * WIN + pos) * DMODEL + c];
        cnt += 1.f;
    }
    y[idx] = val / cnt;
}

// ---------------- launch ----------------
extern "C" void kernel_launch(void* const* d_in, const int* in_sizes, int n_in,
                              void* d_out, int out_size)
{
    const float* x  = (const float*)d_in[0];
    const float* Wq = (const float*)d_in[1];
    const float* bq = (const float*)d_in[2];
    const float* Wk = (const float*)d_in[3];
    const float* bk = (const float*)d_in[4];
    const float* Wv = (const float*)d_in[5];
    const float* bv = (const float*)d_in[6];
    const float* Wo = (const float*)d_in[7];
    const float* bo = (const float*)d_in[8];
    float* out = (float*)d_out;

    float *qb, *kb, *vb, *sb, *owb, *yb;
    cudaGetSymbolAddress((void**)&qb, g_q);
    cudaGetSymbolAddress((void**)&kb, g_k);
    cudaGetSymbolAddress((void**)&vb, g_v);
    cudaGetSymbolAddress((void**)&sb, g_s);
    cudaGetSymbolAddress((void**)&owb, g_ow);
    cudaGetSymbolAddress((void**)&yb, g_y);

    const dim3 gemm_grid(DMODEL / GBN, MTOK / GBM);   // (8, 128)
    sgemm_bias<<<gemm_grid, 256>>>(x, Wq, bq, qb, MTOK, DMODEL, DMODEL);
    sgemm_bias<<<gemm_grid, 256>>>(x, Wk, bk, kb, MTOK, DMODEL, DMODEL);
    sgemm_bias<<<gemm_grid, 256>>>(x, Wv, bv, vb, MTOK, DMODEL, DMODEL);

    const dim3 sc_grid(WIN / ST, WIN / ST, NBW);      // (4, 4, 124)
    win_scores<<<sc_grid, 256>>>(qb, kb, sb);

    win_softmax<<<(NBW * WIN) / 8, 256>>>(sb);

    const dim3 pv_grid(DMODEL / GBN, WIN / GBM, NBW); // (8, 2, 124)
    win_pv<<<pv_grid, 256>>>(sb, vb, owb);

    combine_windows<<<(BATCH * SEQ * DMODEL) / 256, 256>>>(owb, yb);

    sgemm_bias<<<gemm_grid, 256>>>(yb, Wo, bo, out, MTOK, DMODEL, DMODEL);
}

// round 3
// speedup vs baseline: 2.1815x; 2.1815x over previous
#include <cuda_runtime.h>
#include <cuda_bf16.h>
#include <cstdint>

// ---------------- problem constants ----------------
#define BATCH 4
#define SEQ 4096
#define DMODEL 1024
#define WIN 256
#define NWIN 31              // window starts 0,128,...,3840
#define NBW (BATCH * NWIN)   // 124
#define MTOK (BATCH * SEQ)   // 16384

typedef __nv_bfloat16 bf16;

// ---------------- scratch (static device globals, no allocs) ----------------
__device__ float g_q[(size_t)MTOK * DMODEL];
__device__ float g_k[(size_t)MTOK * DMODEL];
__device__ float g_v[(size_t)MTOK * DMODEL];
__device__ float g_s[(size_t)NBW * WIN * WIN];
__device__ float g_ow[(size_t)NBW * WIN * DMODEL];
__device__ float g_y[(size_t)MTOK * DMODEL];

__device__ bf16 g_xh[(size_t)MTOK * DMODEL];
__device__ bf16 g_xl[(size_t)MTOK * DMODEL];
__device__ bf16 g_qh[(size_t)MTOK * DMODEL];
__device__ bf16 g_ql[(size_t)MTOK * DMODEL];
__device__ bf16 g_kh[(size_t)MTOK * DMODEL];
__device__ bf16 g_kl[(size_t)MTOK * DMODEL];
__device__ bf16 g_vth[(size_t)MTOK * DMODEL];   // per-batch transposed V [1024][4096]
__device__ bf16 g_vtl[(size_t)MTOK * DMODEL];
__device__ bf16 g_sh[(size_t)NBW * WIN * WIN];
__device__ bf16 g_sl[(size_t)NBW * WIN * WIN];
__device__ bf16 g_yh[(size_t)MTOK * DMODEL];
__device__ bf16 g_yl[(size_t)MTOK * DMODEL];
__device__ bf16 g_wth[4][(size_t)DMODEL * DMODEL];  // W^T splits (q,k,v,o)
__device__ bf16 g_wtl[4][(size_t)DMODEL * DMODEL];

// ---------------- mma / ldmatrix primitives ----------------
__device__ __forceinline__ void mma16816(float* c, const uint32_t* a,
                                         const uint32_t* b) {
    asm volatile(
        "mma.sync.aligned.m16n8k16.row.col.f32.bf16.bf16.f32 "
        "{%0,%1,%2,%3}, {%4,%5,%6,%7}, {%8,%9}, {%0,%1,%2,%3};"
        : "+f"(c[0]), "+f"(c[1]), "+f"(c[2]), "+f"(c[3])
        : "r"(a[0]), "r"(a[1]), "r"(a[2]), "r"(a[3]), "r"(b[0]), "r"(b[1]));
}

__device__ __forceinline__ void ldsm4(uint32_t* r, uint32_t addr) {
    asm volatile(
        "ldmatrix.sync.aligned.m8n8.x4.shared.b16 {%0,%1,%2,%3}, [%4];"
        : "=r"(r[0]), "=r"(r[1]), "=r"(r[2]), "=r"(r[3])
        : "r"(addr));
}

// ---------------- bf16x3 GEMM core ----------------
// C[M,N] = scale * (A @ Bt^T) + bias, A=[m,k] k-major (split hi/lo),
// Bt=[n,k] k-major (split hi/lo). Block tile 128x128x32, 256 threads.
// Smem rows padded to 40 bf16 (80B): ldmatrix conflict-free.
#define SROW 40

__device__ __forceinline__ void gemm_core(
    const bf16* __restrict__ Ah, const bf16* __restrict__ Al, int lda,
    const bf16* __restrict__ Bh, const bf16* __restrict__ Bl, int ldb,
    const float* __restrict__ bias, float scale,
    float* __restrict__ C, int ldc, int K, int by, int bx)
{
    __shared__ __align__(16) bf16 sAh[128 * SROW];
    __shared__ __align__(16) bf16 sAl[128 * SROW];
    __shared__ __align__(16) bf16 sBh[128 * SROW];
    __shared__ __align__(16) bf16 sBl[128 * SROW];

    const int t = threadIdx.x;
    const int lane = t & 31;
    const int warp = t >> 5;
    const int wm = warp >> 1;     // 0..3 -> 32-row slabs
    const int wn = warp & 1;      // 0..1 -> 64-col slabs

    // gmem staging: slot t covers (row=t>>2, cg=t&3), slot t+256 -> row+64
    const int grow = t >> 2;
    const int gcg = (t & 3) * 8;
    const bf16* pAh = Ah + (size_t)(by + grow) * lda + gcg;
    const bf16* pAl = Al + (size_t)(by + grow) * lda + gcg;
    const bf16* pBh = Bh + (size_t)(bx + grow) * ldb + gcg;
    const bf16* pBl = Bl + (size_t)(bx + grow) * ldb + gcg;
    const size_t astep = (size_t)64 * lda;
    const size_t bstep = (size_t)64 * ldb;

    const int soff = grow * SROW + gcg;

    const uint32_t uAh = (uint32_t)__cvta_generic_to_shared(sAh);
    const uint32_t uAl = (uint32_t)__cvta_generic_to_shared(sAl);
    const uint32_t uBh = (uint32_t)__cvta_generic_to_shared(sBh);
    const uint32_t uBl = (uint32_t)__cvta_generic_to_shared(sBl);

    // ldmatrix lane mapping
    const int lg = lane & 7;
    const int sel = lane >> 3;
    const int radd = (sel & 1) * 8;
    const int cadd = (sel >> 1) * 8;
    const int radd_b = (sel >> 1) * 8;   // B: matrices 2,3 are next n-tile
    const int cadd_b = (sel & 1) * 8;

    float acc[2][8][4];
#pragma unroll
    for (int i = 0; i < 2; i++)
#pragma unroll
        for (int j = 0; j < 8; j++)
#pragma unroll
            for (int q = 0; q < 4; q++) acc[i][j][q] = 0.f;

    uint4 ra0, ra1, rl0, rl1, rb0, rb1, rm0, rm1;
    ra0 = *(const uint4*)(pAh);          ra1 = *(const uint4*)(pAh + astep);
    rl0 = *(const uint4*)(pAl);          rl1 = *(const uint4*)(pAl + astep);
    rb0 = *(const uint4*)(pBh);          rb1 = *(const uint4*)(pBh + bstep);
    rm0 = *(const uint4*)(pBl);          rm1 = *(const uint4*)(pBl + bstep);

    for (int k0 = 0; k0 < K; k0 += 32) {
        *(uint4*)&sAh[soff] = ra0;  *(uint4*)&sAh[soff + 64 * SROW] = ra1;
        *(uint4*)&sAl[soff] = rl0;  *(uint4*)&sAl[soff + 64 * SROW] = rl1;
        *(uint4*)&sBh[soff] = rb0;  *(uint4*)&sBh[soff + 64 * SROW] = rb1;
        *(uint4*)&sBl[soff] = rm0;  *(uint4*)&sBl[soff + 64 * SROW] = rm1;
        __syncthreads();

        if (k0 + 32 < K) {
            const int kn = k0 + 32;
            ra0 = *(const uint4*)(pAh + kn);  ra1 = *(const uint4*)(pAh + astep + kn);
            rl0 = *(const uint4*)(pAl + kn);  rl1 = *(const uint4*)(pAl + astep + kn);
            rb0 = *(const uint4*)(pBh + kn);  rb1 = *(const uint4*)(pBh + bstep + kn);
            rm0 = *(const uint4*)(pBl + kn);  rm1 = *(const uint4*)(pBl + bstep + kn);
        }

#pragma unroll
        for (int kk = 0; kk < 32; kk += 16) {
            uint32_t ah[2][4], al[2][4], bh[4][4], bl[4][4];
#pragma unroll
            for (int i = 0; i < 2; i++) {
                const uint32_t off =
                    ((wm * 32 + i * 16 + radd + lg) * SROW + kk + cadd) * 2;
                ldsm4(ah[i], uAh + off);
                ldsm4(al[i], uAl + off);
            }
#pragma unroll
            for (int jp = 0; jp < 4; jp++) {
                const uint32_t off =
                    ((wn * 64 + jp * 16 + radd_b + lg) * SROW + kk + cadd_b) * 2;
                ldsm4(bh[jp], uBh + off);
                ldsm4(bl[jp], uBl + off);
            }
#pragma unroll
            for (int i = 0; i < 2; i++)
#pragma unroll
                for (int j = 0; j < 8; j++) {
                    const uint32_t* bhp = &bh[j >> 1][(j & 1) * 2];
                    const uint32_t* blp = &bl[j >> 1][(j & 1) * 2];
                    mma16816(acc[i][j], ah[i], bhp);
                    mma16816(acc[i][j], al[i], bhp);
                    mma16816(acc[i][j], ah[i], blp);
                }
        }
        __syncthreads();
    }

    // epilogue
    const int lrow = lane >> 2;
    const int lcol = (lane & 3) * 2;
#pragma unroll
    for (int i = 0; i < 2; i++) {
        const int r0 = by + wm * 32 + i * 16 + lrow;
#pragma unroll
        for (int j = 0; j < 8; j++) {
            const int c = bx + wn * 64 + j * 8 + lcol;
            float b0 = 0.f, b1 = 0.f;
            if (bias) { b0 = bias[c]; b1 = bias[c + 1]; }
            float2 v0, v1;
            v0.x = acc[i][j][0] * scale + b0;
            v0.y = acc[i][j][1] * scale + b1;
            v1.x = acc[i][j][2] * scale + b0;
            v1.y = acc[i][j][3] * scale + b1;
            *(float2*)&C[(size_t)r0 * ldc + c] = v0;
            *(float2*)&C[(size_t)(r0 + 8) * ldc + c] = v1;
        }
    }
}

// ---------------- GEMM wrappers ----------------
__global__ __launch_bounds__(256) void gemm_proj(
    const bf16* __restrict__ Ah, const bf16* __restrict__ Al,
    const bf16* __restrict__ Bth, const bf16* __restrict__ Btl,
    const float* __restrict__ bias, float* __restrict__ C)
{
    gemm_core(Ah, Al, DMODEL, Bth, Btl, DMODEL, bias, 1.f, C, DMODEL,
              DMODEL, blockIdx.y * 128, blockIdx.x * 128);
}

__global__ __launch_bounds__(256) void gemm_scores(
    const bf16* __restrict__ qh, const bf16* __restrict__ ql,
    const bf16* __restrict__ kh, const bf16* __restrict__ kl,
    float* __restrict__ s)
{
    const int z = blockIdx.z;
    const int b = z / NWIN;
    const int w = z - b * NWIN;
    const size_t off = ((size_t)b * SEQ + 128 * w) * DMODEL;
    gemm_core(qh + off, ql + off, DMODEL, kh + off, kl + off, DMODEL,
              nullptr, 0.125f, s + (size_t)z * WIN * WIN, WIN,
              DMODEL, blockIdx.y * 128, blockIdx.x * 128);
}

__global__ __launch_bounds__(256) void gemm_pv(
    const bf16* __restrict__ sh, const bf16* __restrict__ sl,
    const bf16* __restrict__ vth, const bf16* __restrict__ vtl,
    float* __restrict__ ow)
{
    const int z = blockIdx.z;
    const int b = z / NWIN;
    const int w = z - b * NWIN;
    const size_t aoff = (size_t)z * WIN * WIN;
    const size_t boff = (size_t)b * DMODEL * SEQ + 128 * w;
    gemm_core(sh + aoff, sl + aoff, WIN, vth + boff, vtl + boff, SEQ,
              nullptr, 1.f, ow + (size_t)z * WIN * DMODEL, DMODEL,
              WIN, blockIdx.y * 128, blockIdx.x * 128);
}

// ---------------- split kernels ----------------
__global__ __launch_bounds__(256) void split_plain(
    const float* __restrict__ src, bf16* __restrict__ h,
    bf16* __restrict__ l, int n4)
{
    for (int i = blockIdx.x * 256 + threadIdx.x; i < n4;
         i += gridDim.x * 256) {
        float4 v = ((const float4*)src)[i];
        bf16 hx = __float2bfloat16_rn(v.x);
        bf16 hy = __float2bfloat16_rn(v.y);
        bf16 hz = __float2bfloat16_rn(v.z);
        bf16 hw = __float2bfloat16_rn(v.w);
        __nv_bfloat162 h01{hx, hy}, h23{hz, hw};
        __nv_bfloat162 l01{__float2bfloat16_rn(v.x - __bfloat162float(hx)),
                           __float2bfloat16_rn(v.y - __bfloat162float(hy))};
        __nv_bfloat162 l23{__float2bfloat16_rn(v.z - __bfloat162float(hz)),
                           __float2bfloat16_rn(v.w - __bfloat162float(hw))};
        ((__nv_bfloat162*)h)[2 * i]     = h01;
        ((__nv_bfloat162*)h)[2 * i + 1] = h23;
        ((__nv_bfloat162*)l)[2 * i]     = l01;
        ((__nv_bfloat162*)l)[2 * i + 1] = l23;
    }
}

// transpose + split: src [R][Cc] fp32 -> dst [Cc][R] bf16 hi/lo
__global__ __launch_bounds__(256) void split_T(
    const float* __restrict__ src, bf16* __restrict__ dh,
    bf16* __restrict__ dl, int R, int Cc, size_t sStride, size_t dStride)
{
    __shared__ float tile[32][33];
    const float* S = src + blockIdx.z * sStride;
    bf16* H = dh + blockIdx.z * dStride;
    bf16* L = dl + blockIdx.z * dStride;

    const int c0 = blockIdx.x * 32;
    const int r0 = blockIdx.y * 32;
    const int tx = threadIdx.x & 31;
    const int ty = threadIdx.x >> 5;

#pragma unroll
    for (int k = 0; k < 4; k++)
        tile[ty + 8 * k][tx] = S[(size_t)(r0 + ty + 8 * k) * Cc + c0 + tx];
    __syncthreads();

#pragma unroll
    for (int k = 0; k < 4; k++) {
        const float v = tile[tx][ty + 8 * k];
        const bf16 hv = __float2bfloat16_rn(v);
        const bf16 lv = __float2bfloat16_rn(v - __bfloat162float(hv));
        const size_t o = (size_t)(c0 + ty + 8 * k) * R + r0 + tx;
        H[o] = hv;
        L[o] = lv;
    }
}

// ---------------- softmax over 256-wide rows (warp per row) ----------------
__global__ __launch_bounds__(256) void win_softmax(float* __restrict__ s)
{
    const int row = blockIdx.x * 8 + (threadIdx.x >> 5);
    const int lane = threadIdx.x & 31;
    float* r = s + (size_t)row * WIN;

    float v[8];
    float m = -1e30f;
#pragma unroll
    for (int j = 0; j < 8; j++) {
        v[j] = r[lane + 32 * j];
        m = fmaxf(m, v[j]);
    }
#pragma unroll
    for (int o = 16; o > 0; o >>= 1)
        m = fmaxf(m, __shfl_xor_sync(0xffffffffu, m, o));

    float sum = 0.f;
#pragma unroll
    for (int j = 0; j < 8; j++) { v[j] = expf(v[j] - m); sum += v[j]; }
#pragma unroll
    for (int o = 16; o > 0; o >>= 1)
        sum += __shfl_xor_sync(0xffffffffu, sum, o);
    const float inv = 1.f / sum;

#pragma unroll
    for (int j = 0; j < 8; j++)
        r[lane + 32 * j] = v[j] * inv;
}

// ---------------- combine overlapping windows ----------------
__global__ __launch_bounds__(256) void combine_windows(
    const float* __restrict__ ow, float* __restrict__ y)
{
    const int idx = blockIdx.x * 256 + threadIdx.x;
    const int c = idx & (DMODEL - 1);
    const int bt = idx >> 10;
    const int t = bt & (SEQ - 1);
    const int b = bt >> 12;

    const int w1 = t >> 7;
    float val = 0.f, cnt = 0.f;
#pragma unroll
    for (int dw = -1; dw <= 0; dw++) {
        const int w = w1 + dw;
        if (w < 0 || w >= NWIN) continue;
        const int pos = t - 128 * w;
        if (pos < 0 || pos >= WIN) continue;
        val += ow[(((size_t)(b * NWIN + w)) * WIN + pos) * DMODEL + c];
        cnt += 1.f;
    }
    y[idx] = val / cnt;
}

// ---------------- launch ----------------
extern "C" void kernel_launch(void* const* d_in, const int* in_sizes, int n_in,
                              void* d_out, int out_size)
{
    const float* x  = (const float*)d_in[0];
    const float* Wq = (const float*)d_in[1];
    const float* bq = (const float*)d_in[2];
    const float* Wk = (const float*)d_in[3];
    const float* bk = (const float*)d_in[4];
    const float* Wv = (const float*)d_in[5];
    const float* bv = (const float*)d_in[6];
    const float* Wo = (const float*)d_in[7];
    const float* bo = (const float*)d_in[8];
    float* out = (float*)d_out;

    float *qb, *kb, *vb, *sb, *owb, *yb;
    cudaGetSymbolAddress((void**)&qb, g_q);
    cudaGetSymbolAddress((void**)&kb, g_k);
    cudaGetSymbolAddress((void**)&vb, g_v);
    cudaGetSymbolAddress((void**)&sb, g_s);
    cudaGetSymbolAddress((void**)&owb, g_ow);
    cudaGetSymbolAddress((void**)&yb, g_y);
    bf16 *xh, *xl, *qh, *ql, *kh, *kl, *vth, *vtl, *sh, *sl, *yh, *yl;
    bf16 (*wth)[DMODEL * DMODEL], (*wtl)[DMODEL * DMODEL];
    cudaGetSymbolAddress((void**)&xh, g_xh);
    cudaGetSymbolAddress((void**)&xl, g_xl);
    cudaGetSymbolAddress((void**)&qh, g_qh);
    cudaGetSymbolAddress((void**)&ql, g_ql);
    cudaGetSymbolAddress((void**)&kh, g_kh);
    cudaGetSymbolAddress((void**)&kl, g_kl);
    cudaGetSymbolAddress((void**)&vth, g_vth);
    cudaGetSymbolAddress((void**)&vtl, g_vtl);
    cudaGetSymbolAddress((void**)&sh, g_sh);
    cudaGetSymbolAddress((void**)&sl, g_sl);
    cudaGetSymbolAddress((void**)&yh, g_yh);
    cudaGetSymbolAddress((void**)&yl, g_yl);
    cudaGetSymbolAddress((void**)&wth, g_wth);
    cudaGetSymbolAddress((void**)&wtl, g_wtl);

    // weight transpose+split (W[K][N] -> Wt[N][K])
    const dim3 wtg(32, 32, 1);
    split_T<<<wtg, 256>>>(Wq, wth[0], wtl[0], DMODEL, DMODEL, 0, 0);
    split_T<<<wtg, 256>>>(Wk, wth[1], wtl[1], DMODEL, DMODEL, 0, 0);
    split_T<<<wtg, 256>>>(Wv, wth[2], wtl[2], DMODEL, DMODEL, 0, 0);
    split_T<<<wtg, 256>>>(Wo, wth[3], wtl[3], DMODEL, DMODEL, 0, 0);

    split_plain<<<2048, 256>>>(x, xh, xl, MTOK * DMODEL / 4);

    const dim3 pg(DMODEL / 128, MTOK / 128);   // (8, 128)
    gemm_proj<<<pg, 256>>>(xh, xl, wth[0], wtl[0], bq, qb);
    gemm_proj<<<pg, 256>>>(xh, xl, wth[1], wtl[1], bk, kb);
    gemm_proj<<<pg, 256>>>(xh, xl, wth[2], wtl[2], bv, vb);

    split_plain<<<2048, 256>>>(qb, qh, ql, MTOK * DMODEL / 4);
    split_plain<<<2048, 256>>>(kb, kh, kl, MTOK * DMODEL / 4);
    split_T<<<dim3(32, SEQ / 32, BATCH), 256>>>(
        vb, vth, vtl, SEQ, DMODEL,
        (size_t)SEQ * DMODEL, (size_t)SEQ * DMODEL);

    gemm_scores<<<dim3(2, 2, NBW), 256>>>(qh, ql, kh, kl, sb);

    win_softmax<<<(NBW * WIN) / 8, 256>>>(sb);

    split_plain<<<2048, 256>>>(sb, sh, sl, NBW * WIN * WIN / 4);

    gemm_pv<<<dim3(DMODEL / 128, 2, NBW), 256>>>(sh, sl, vth, vtl, owb);

    combine_windows<<<(MTOK * DMODEL) / 256, 256>>>(owb, yb);

    split_plain<<<2048, 256>>>(yb, yh, yl, MTOK * DMODEL / 4);
    gemm_proj<<<pg, 256>>>(yh, yl, wth[3], wtl[3], bo, out);
}

// round 4
// speedup vs baseline: 2.4412x; 1.1190x over previous
#include <cuda_runtime.h>
#include <cuda_bf16.h>
#include <cstdint>

// ---------------- problem constants ----------------
#define BATCH 4
#define SEQ 4096
#define DMODEL 1024
#define WIN 256
#define NWIN 31              // window starts 0,128,...,3840
#define NBW (BATCH * NWIN)   // 124
#define MTOK (BATCH * SEQ)   // 16384

typedef __nv_bfloat16 bf16;

// ---------------- scratch (static device globals, no allocs) ----------------
__device__ float g_v[(size_t)MTOK * DMODEL];
__device__ float g_s[(size_t)NBW * WIN * WIN];
__device__ float g_ow[(size_t)NBW * WIN * DMODEL];

__device__ bf16 g_xh[(size_t)MTOK * DMODEL];
__device__ bf16 g_xl[(size_t)MTOK * DMODEL];
__device__ bf16 g_qh[(size_t)MTOK * DMODEL];
__device__ bf16 g_ql[(size_t)MTOK * DMODEL];
__device__ bf16 g_kh[(size_t)MTOK * DMODEL];
__device__ bf16 g_kl[(size_t)MTOK * DMODEL];
__device__ bf16 g_vth[(size_t)MTOK * DMODEL];   // per-batch V^T [1024][4096]
__device__ bf16 g_vtl[(size_t)MTOK * DMODEL];
__device__ bf16 g_sh[(size_t)NBW * WIN * WIN];
__device__ bf16 g_sl[(size_t)NBW * WIN * WIN];
__device__ bf16 g_yh[(size_t)MTOK * DMODEL];
__device__ bf16 g_yl[(size_t)MTOK * DMODEL];
__device__ bf16 g_wth[4][(size_t)DMODEL * DMODEL];  // W^T splits (q,k,v,o)
__device__ bf16 g_wtl[4][(size_t)DMODEL * DMODEL];

// ---------------- primitives ----------------
__device__ __forceinline__ void mma16816(float* c, const uint32_t* a,
                                         const uint32_t* b) {
    asm volatile(
        "mma.sync.aligned.m16n8k16.row.col.f32.bf16.bf16.f32 "
        "{%0,%1,%2,%3}, {%4,%5,%6,%7}, {%8,%9}, {%0,%1,%2,%3};"
        : "+f"(c[0]), "+f"(c[1]), "+f"(c[2]), "+f"(c[3])
        : "r"(a[0]), "r"(a[1]), "r"(a[2]), "r"(a[3]), "r"(b[0]), "r"(b[1]));
}

__device__ __forceinline__ void ldsm4(uint32_t* r, uint32_t addr) {
    asm volatile(
        "ldmatrix.sync.aligned.m8n8.x4.shared.b16 {%0,%1,%2,%3}, [%4];"
        : "=r"(r[0]), "=r"(r[1]), "=r"(r[2]), "=r"(r[3])
        : "r"(addr));
}

__device__ __forceinline__ void cpa16(uint32_t s, const void* g) {
    asm volatile("cp.async.cg.shared.global [%0], [%1], 16;"
                 :: "r"(s), "l"(g) : "memory");
}
__device__ __forceinline__ void cpa_commit() {
    asm volatile("cp.async.commit_group;" ::: "memory");
}
__device__ __forceinline__ void cpa_wait1() {
    asm volatile("cp.async.wait_group 1;" ::: "memory");
}
__device__ __forceinline__ void cpa_wait0() {
    asm volatile("cp.async.wait_group 0;" ::: "memory");
}

__device__ __forceinline__ bf16 hi_of(float v) { return __float2bfloat16_rn(v); }
__device__ __forceinline__ bf16 lo_of(float v, bf16 h) {
    return __float2bfloat16_rn(v - __bfloat162float(h));
}

// ---------------- bf16x3 GEMM core (cp.async double-buffered) ----------------
// C = scale * (A @ Bt^T) + bias. A=[m,k] k-major split hi/lo, Bt=[n,k]
// k-major split hi/lo. Block 128x128x32, 256 threads.
// OM=0: write fp32 C. OM=1: write bf16 hi/lo pair (Ch, Cl).
#define SROW 40
#define MATB (128 * SROW * 2)     // bytes per matrix per stage
#define STB (4 * MATB)            // bytes per stage
#define GSMEM (2 * STB)           // 81920 bytes dynamic smem

template <int OM>
__device__ __forceinline__ void gemm_core(
    const bf16* __restrict__ Ah, const bf16* __restrict__ Al, int lda,
    const bf16* __restrict__ Bh, const bf16* __restrict__ Bl, int ldb,
    const float* __restrict__ bias, float scale,
    float* __restrict__ C, bf16* __restrict__ Ch, bf16* __restrict__ Cl,
    int ldc, int K, int by, int bx)
{
    extern __shared__ __align__(16) char smbuf[];
    const uint32_t smu = (uint32_t)__cvta_generic_to_shared(smbuf);

    const int t = threadIdx.x;
    const int lane = t & 31;
    const int warp = t >> 5;
    const int wm = warp >> 1;     // 0..3 -> 32-row slabs
    const int wn = warp & 1;      // 0..1 -> 64-col slabs

    const int grow = t >> 2;            // 0..63
    const int gcg = (t & 3) * 8;        // 0,8,16,24
    const bf16* pAh = Ah + (size_t)(by + grow) * lda + gcg;
    const bf16* pAl = Al + (size_t)(by + grow) * lda + gcg;
    const bf16* pBh = Bh + (size_t)(bx + grow) * ldb + gcg;
    const bf16* pBl = Bl + (size_t)(bx + grow) * ldb + gcg;
    const size_t astep = (size_t)64 * lda;
    const size_t bstep = (size_t)64 * ldb;

    const uint32_t soffB = (uint32_t)(grow * SROW + gcg) * 2;
    const uint32_t r2 = 64 * SROW * 2;

    // ldmatrix lane mapping
    const int lg = lane & 7;
    const int sel = lane >> 3;
    const int radd = (sel & 1) * 8;
    const int cadd = (sel >> 1) * 8;
    const int radd_b = (sel >> 1) * 8;
    const int cadd_b = (sel & 1) * 8;

    float acc[2][8][4];
#pragma unroll
    for (int i = 0; i < 2; i++)
#pragma unroll
        for (int j = 0; j < 8; j++)
#pragma unroll
            for (int q = 0; q < 4; q++) acc[i][j][q] = 0.f;

#define ISSUE(kt, st)                                                     \
    {                                                                     \
        const size_t ko = (size_t)(kt) * 32;                              \
        const uint32_t d = smu + (st) * STB + soffB;                      \
        cpa16(d, pAh + ko);                                               \
        cpa16(d + r2, pAh + astep + ko);                                  \
        cpa16(d + MATB, pAl + ko);                                        \
        cpa16(d + MATB + r2, pAl + astep + ko);                           \
        cpa16(d + 2 * MATB, pBh + ko);                                    \
        cpa16(d + 2 * MATB + r2, pBh + bstep + ko);                       \
        cpa16(d + 3 * MATB, pBl + ko);                                    \
        cpa16(d + 3 * MATB + r2, pBl + bstep + ko);                       \
    }

    const int nt = K / 32;
    ISSUE(0, 0);
    cpa_commit();

    for (int kt = 0; kt < nt; kt++) {
        const int cur = kt & 1;
        if (kt + 1 < nt) {
            ISSUE(kt + 1, cur ^ 1);
            cpa_commit();
            cpa_wait1();
        } else {
            cpa_wait0();
        }
        __syncthreads();

        const uint32_t bAh = smu + cur * STB;
        const uint32_t bAl = bAh + MATB;
        const uint32_t bBh = bAh + 2 * MATB;
        const uint32_t bBl = bAh + 3 * MATB;

#pragma unroll
        for (int kk = 0; kk < 32; kk += 16) {
            uint32_t ah[2][4], al[2][4], bh[4][4], bl[4][4];
#pragma unroll
            for (int i = 0; i < 2; i++) {
                const uint32_t off =
                    ((wm * 32 + i * 16 + radd + lg) * SROW + kk + cadd) * 2;
                ldsm4(ah[i], bAh + off);
                ldsm4(al[i], bAl + off);
            }
#pragma unroll
            for (int jp = 0; jp < 4; jp++) {
                const uint32_t off =
                    ((wn * 64 + jp * 16 + radd_b + lg) * SROW + kk + cadd_b) * 2;
                ldsm4(bh[jp], bBh + off);
                ldsm4(bl[jp], bBl + off);
            }
#pragma unroll
            for (int i = 0; i < 2; i++)
#pragma unroll
                for (int j = 0; j < 8; j++) {
                    const uint32_t* bhp = &bh[j >> 1][(j & 1) * 2];
                    const uint32_t* blp = &bl[j >> 1][(j & 1) * 2];
                    mma16816(acc[i][j], ah[i], bhp);
                    mma16816(acc[i][j], al[i], bhp);
                    mma16816(acc[i][j], ah[i], blp);
                }
        }
        __syncthreads();
    }
#undef ISSUE

    // epilogue
    const int lrow = lane >> 2;
    const int lcol = (lane & 3) * 2;
#pragma unroll
    for (int i = 0; i < 2; i++) {
        const int r0 = by + wm * 32 + i * 16 + lrow;
#pragma unroll
        for (int j = 0; j < 8; j++) {
            const int c = bx + wn * 64 + j * 8 + lcol;
            float b0 = 0.f, b1 = 0.f;
            if (bias) { b0 = bias[c]; b1 = bias[c + 1]; }
            const float v00 = acc[i][j][0] * scale + b0;
            const float v01 = acc[i][j][1] * scale + b1;
            const float v10 = acc[i][j][2] * scale + b0;
            const float v11 = acc[i][j][3] * scale + b1;
            if (OM == 0) {
                *(float2*)&C[(size_t)r0 * ldc + c] = make_float2(v00, v01);
                *(float2*)&C[(size_t)(r0 + 8) * ldc + c] = make_float2(v10, v11);
            } else {
                const bf16 h00 = hi_of(v00), h01 = hi_of(v01);
                const bf16 h10 = hi_of(v10), h11 = hi_of(v11);
                __nv_bfloat162 hp0{h00, h01}, hp1{h10, h11};
                __nv_bfloat162 lp0{lo_of(v00, h00), lo_of(v01, h01)};
                __nv_bfloat162 lp1{lo_of(v10, h10), lo_of(v11, h11)};
                *(__nv_bfloat162*)&Ch[(size_t)r0 * ldc + c] = hp0;
                *(__nv_bfloat162*)&Ch[(size_t)(r0 + 8) * ldc + c] = hp1;
                *(__nv_bfloat162*)&Cl[(size_t)r0 * ldc + c] = lp0;
                *(__nv_bfloat162*)&Cl[(size_t)(r0 + 8) * ldc + c] = lp1;
            }
        }
    }
}

// ---------------- GEMM wrappers ----------------
__global__ __launch_bounds__(256) void gemm_proj_b(
    const bf16* __restrict__ Ah, const bf16* __restrict__ Al,
    const bf16* __restrict__ Bth, const bf16* __restrict__ Btl,
    const float* __restrict__ bias, bf16* __restrict__ Ch,
    bf16* __restrict__ Cl)
{
    gemm_core<1>(Ah, Al, DMODEL, Bth, Btl, DMODEL, bias, 1.f,
                 nullptr, Ch, Cl, DMODEL, DMODEL,
                 blockIdx.y * 128, blockIdx.x * 128);
}

__global__ __launch_bounds__(256) void gemm_proj_f(
    const bf16* __restrict__ Ah, const bf16* __restrict__ Al,
    const bf16* __restrict__ Bth, const bf16* __restrict__ Btl,
    const float* __restrict__ bias, float* __restrict__ C)
{
    gemm_core<0>(Ah, Al, DMODEL, Bth, Btl, DMODEL, bias, 1.f,
                 C, nullptr, nullptr, DMODEL, DMODEL,
                 blockIdx.y * 128, blockIdx.x * 128);
}

__global__ __launch_bounds__(256) void gemm_scores(
    const bf16* __restrict__ qh, const bf16* __restrict__ ql,
    const bf16* __restrict__ kh, const bf16* __restrict__ kl,
    float* __restrict__ s)
{
    const int z = blockIdx.z;
    const int b = z / NWIN;
    const int w = z - b * NWIN;
    const size_t off = ((size_t)b * SEQ + 128 * w) * DMODEL;
    gemm_core<0>(qh + off, ql + off, DMODEL, kh + off, kl + off, DMODEL,
                 nullptr, 0.125f, s + (size_t)z * WIN * WIN, nullptr, nullptr,
                 WIN, DMODEL, blockIdx.y * 128, blockIdx.x * 128);
}

__global__ __launch_bounds__(256) void gemm_pv(
    const bf16* __restrict__ sh, const bf16* __restrict__ sl,
    const bf16* __restrict__ vth, const bf16* __restrict__ vtl,
    float* __restrict__ ow)
{
    const int z = blockIdx.z;
    const int b = z / NWIN;
    const int w = z - b * NWIN;
    const size_t aoff = (size_t)z * WIN * WIN;
    const size_t boff = (size_t)b * DMODEL * SEQ + 128 * w;
    gemm_core<0>(sh + aoff, sl + aoff, WIN, vth + boff, vtl + boff, SEQ,
                 nullptr, 1.f, ow + (size_t)z * WIN * DMODEL, nullptr, nullptr,
                 DMODEL, WIN, blockIdx.y * 128, blockIdx.x * 128);
}

// ---------------- split kernels ----------------
__global__ __launch_bounds__(256) void split_plain(
    const float* __restrict__ src, bf16* __restrict__ h,
    bf16* __restrict__ l, int n4)
{
    for (int i = blockIdx.x * 256 + threadIdx.x; i < n4;
         i += gridDim.x * 256) {
        float4 v = ((const float4*)src)[i];
        bf16 hx = hi_of(v.x), hy = hi_of(v.y), hz = hi_of(v.z), hw = hi_of(v.w);
        __nv_bfloat162 h01{hx, hy}, h23{hz, hw};
        __nv_bfloat162 l01{lo_of(v.x, hx), lo_of(v.y, hy)};
        __nv_bfloat162 l23{lo_of(v.z, hz), lo_of(v.w, hw)};
        ((__nv_bfloat162*)h)[2 * i]     = h01;
        ((__nv_bfloat162*)h)[2 * i + 1] = h23;
        ((__nv_bfloat162*)l)[2 * i]     = l01;
        ((__nv_bfloat162*)l)[2 * i + 1] = l23;
    }
}

// transpose + split: src [R][Cc] fp32 -> dst [Cc][R] bf16 hi/lo
__global__ __launch_bounds__(256) void split_T(
    const float* __restrict__ src, bf16* __restrict__ dh,
    bf16* __restrict__ dl, int R, int Cc, size_t sStride, size_t dStride)
{
    __shared__ float tile[32][33];
    const float* S = src + blockIdx.z * sStride;
    bf16* H = dh + blockIdx.z * dStride;
    bf16* L = dl + blockIdx.z * dStride;

    const int c0 = blockIdx.x * 32;
    const int r0 = blockIdx.y * 32;
    const int tx = threadIdx.x & 31;
    const int ty = threadIdx.x >> 5;

#pragma unroll
    for (int k = 0; k < 4; k++)
        tile[ty + 8 * k][tx] = S[(size_t)(r0 + ty + 8 * k) * Cc + c0 + tx];
    __syncthreads();

#pragma unroll
    for (int k = 0; k < 4; k++) {
        const float v = tile[tx][ty + 8 * k];
        const bf16 hv = hi_of(v);
        const bf16 lv = lo_of(v, hv);
        const size_t o = (size_t)(c0 + ty + 8 * k) * R + r0 + tx;
        H[o] = hv;
        L[o] = lv;
    }
}

// ---------------- softmax + split (warp per 256-wide row) ----------------
__global__ __launch_bounds__(256) void win_softmax_split(
    const float* __restrict__ s, bf16* __restrict__ sh, bf16* __restrict__ sl)
{
    const int row = blockIdx.x * 8 + (threadIdx.x >> 5);
    const int lane = threadIdx.x & 31;
    const float* r = s + (size_t)row * WIN;

    float v[8];
    float m = -1e30f;
#pragma unroll
    for (int j = 0; j < 8; j++) {
        v[j] = r[lane + 32 * j];
        m = fmaxf(m, v[j]);
    }
#pragma unroll
    for (int o = 16; o > 0; o >>= 1)
        m = fmaxf(m, __shfl_xor_sync(0xffffffffu, m, o));

    float sum = 0.f;
#pragma unroll
    for (int j = 0; j < 8; j++) { v[j] = expf(v[j] - m); sum += v[j]; }
#pragma unroll
    for (int o = 16; o > 0; o >>= 1)
        sum += __shfl_xor_sync(0xffffffffu, sum, o);
    const float inv = 1.f / sum;

#pragma unroll
    for (int j = 0; j < 8; j++) {
        const float p = v[j] * inv;
        const bf16 h = hi_of(p);
        const size_t o = (size_t)row * WIN + lane + 32 * j;
        sh[o] = h;
        sl[o] = lo_of(p, h);
    }
}

// ---------------- combine + split ----------------
__global__ __launch_bounds__(256) void combine_split(
    const float* __restrict__ ow, bf16* __restrict__ yh, bf16* __restrict__ yl)
{
    const int idx = blockIdx.x * 256 + threadIdx.x;
    const int c = idx & (DMODEL - 1);
    const int bt = idx >> 10;
    const int t = bt & (SEQ - 1);
    const int b = bt >> 12;

    const int w1 = t >> 7;
    float val = 0.f, cnt = 0.f;
#pragma unroll
    for (int dw = -1; dw <= 0; dw++) {
        const int w = w1 + dw;
        if (w < 0 || w >= NWIN) continue;
        const int pos = t - 128 * w;
        if (pos < 0 || pos >= WIN) continue;
        val += ow[(((size_t)(b * NWIN + w)) * WIN + pos) * DMODEL + c];
        cnt += 1.f;
    }
    const float y = val / cnt;
    const bf16 h = hi_of(y);
    yh[idx] = h;
    yl[idx] = lo_of(y, h);
}

// ---------------- launch ----------------
extern "C" void kernel_launch(void* const* d_in, const int* in_sizes, int n_in,
                              void* d_out, int out_size)
{
    const float* x  = (const float*)d_in[0];
    const float* Wq = (const float*)d_in[1];
    const float* bq = (const float*)d_in[2];
    const float* Wk = (const float*)d_in[3];
    const float* bk = (const float*)d_in[4];
    const float* Wv = (const float*)d_in[5];
    const float* bv = (const float*)d_in[6];
    const float* Wo = (const float*)d_in[7];
    const float* bo = (const float*)d_in[8];
    float* out = (float*)d_out;

    float *vb, *sb, *owb;
    cudaGetSymbolAddress((void**)&vb, g_v);
    cudaGetSymbolAddress((void**)&sb, g_s);
    cudaGetSymbolAddress((void**)&owb, g_ow);
    bf16 *xh, *xl, *qh, *ql, *kh, *kl, *vth, *vtl, *sh, *sl, *yh, *yl;
    bf16 (*wth)[DMODEL * DMODEL], (*wtl)[DMODEL * DMODEL];
    cudaGetSymbolAddress((void**)&xh, g_xh);
    cudaGetSymbolAddress((void**)&xl, g_xl);
    cudaGetSymbolAddress((void**)&qh, g_qh);
    cudaGetSymbolAddress((void**)&ql, g_ql);
    cudaGetSymbolAddress((void**)&kh, g_kh);
    cudaGetSymbolAddress((void**)&kl, g_kl);
    cudaGetSymbolAddress((void**)&vth, g_vth);
    cudaGetSymbolAddress((void**)&vtl, g_vtl);
    cudaGetSymbolAddress((void**)&sh, g_sh);
    cudaGetSymbolAddress((void**)&sl, g_sl);
    cudaGetSymbolAddress((void**)&yh, g_yh);
    cudaGetSymbolAddress((void**)&yl, g_yl);
    cudaGetSymbolAddress((void**)&wth, g_wth);
    cudaGetSymbolAddress((void**)&wtl, g_wtl);

    cudaFuncSetAttribute(gemm_proj_b,
        cudaFuncAttributeMaxDynamicSharedMemorySize, GSMEM);
    cudaFuncSetAttribute(gemm_proj_f,
        cudaFuncAttributeMaxDynamicSharedMemorySize, GSMEM);
    cudaFuncSetAttribute(gemm_scores,
        cudaFuncAttributeMaxDynamicSharedMemorySize, GSMEM);
    cudaFuncSetAttribute(gemm_pv,
        cudaFuncAttributeMaxDynamicSharedMemorySize, GSMEM);

    // weight transpose+split (W[K][N] -> Wt[N][K])
    const dim3 wtg(32, 32, 1);
    split_T<<<wtg, 256>>>(Wq, wth[0], wtl[0], DMODEL, DMODEL, 0, 0);
    split_T<<<wtg, 256>>>(Wk, wth[1], wtl[1], DMODEL, DMODEL, 0, 0);
    split_T<<<wtg, 256>>>(Wv, wth[2], wtl[2], DMODEL, DMODEL, 0, 0);
    split_T<<<wtg, 256>>>(Wo, wth[3], wtl[3], DMODEL, DMODEL, 0, 0);

    split_plain<<<2048, 256>>>(x, xh, xl, MTOK * DMODEL / 4);

    const dim3 pg(DMODEL / 128, MTOK / 128);   // (8, 128)
    gemm_proj_b<<<pg, 256, GSMEM>>>(xh, xl, wth[0], wtl[0], bq, qh, ql);
    gemm_proj_b<<<pg, 256, GSMEM>>>(xh, xl, wth[1], wtl[1], bk, kh, kl);
    gemm_proj_f<<<pg, 256, GSMEM>>>(xh, xl, wth[2], wtl[2], bv, vb);

    split_T<<<dim3(32, SEQ / 32, BATCH), 256>>>(
        vb, vth, vtl, SEQ, DMODEL,
        (size_t)SEQ * DMODEL, (size_t)SEQ * DMODEL);

    gemm_scores<<<dim3(2, 2, NBW), 256, GSMEM>>>(qh, ql, kh, kl, sb);

    win_softmax_split<<<(NBW * WIN) / 8, 256>>>(sb, sh, sl);

    gemm_pv<<<dim3(DMODEL / 128, 2, NBW), 256, GSMEM>>>(sh, sl, vth, vtl, owb);

    combine_split<<<(MTOK * DMODEL) / 256, 256>>>(owb, yh, yl);

    gemm_proj_f<<<pg, 256, GSMEM>>>(yh, yl, wth[3], wtl[3], bo, out);
}